// round 12
// baseline (speedup 1.0000x reference)
#include <cuda_runtime.h>
#include <cuda_bf16.h>
#include <cstdint>

// LengthRegulator: out[b, t, :] = phoneme[b, tok(b,t), :]
// tok(b,t) = searchsorted_right(inclusive_cumsum(durations[b,:]), t), clip N-1.
// Shapes (fixed): B=16, N=256, D=512, T=2048. float32.
//
// Dual-path store experiment: frames 0-15 stored via LSU STG.128, frames
// 16-31 staged in smem and stored via one 32KB cp.async.bulk (TMA path).
// Tests whether LSU-store and TMA-store capacity in front of the LTS sum.

#define LR_B 16
#define LR_N 256
#define LR_D 512
#define LR_T 2048
#define FPB 32
#define THREADS 256
#define VPF 128                          // float4 per 2KB frame
#define HALF (FPB / 2)                   // 16 frames per path
#define STAGE_BYTES (HALF * VPF * 16)    // 32 KB

__device__ __forceinline__ uint32_t smem_u32(const void* p) {
    uint32_t a;
    asm("{ .reg .u64 t; cvta.to.shared.u64 t, %1; cvt.u32.u64 %0, t; }"
        : "=r"(a) : "l"(p));
    return a;
}

__global__ __launch_bounds__(THREADS)
void length_regulator_dual(const float4* __restrict__ phoneme4,
                           const int* __restrict__ durations,
                           float4* __restrict__ out4)
{
    __shared__ __align__(128) float4 s_stage[HALF * VPF];  // 32 KB
    __shared__ int s_ends[LR_N];
    __shared__ int s_tok[FPB];

    const int b = blockIdx.y;
    const int frame_base = blockIdx.x * FPB;
    const int tid = threadIdx.x;

    // ---- warp 0: shuffle scan + 32 binary searches ----
    if (tid < 32) {
        const int lane = tid;
        const int4* drow = (const int4*)(durations + b * LR_N);
        int4 a = drow[lane * 2 + 0];
        int4 c = drow[lane * 2 + 1];
        int e0 = a.x;
        int e1 = e0 + a.y;
        int e2 = e1 + a.z;
        int e3 = e2 + a.w;
        int e4 = e3 + c.x;
        int e5 = e4 + c.y;
        int e6 = e5 + c.z;
        int e7 = e6 + c.w;
        int x = e7;
        #pragma unroll
        for (int off = 1; off < 32; off <<= 1) {
            int y = __shfl_up_sync(0xffffffffu, x, off);
            if (lane >= off) x += y;
        }
        const int excl = x - e7;
        s_ends[lane * 8 + 0] = e0 + excl;
        s_ends[lane * 8 + 1] = e1 + excl;
        s_ends[lane * 8 + 2] = e2 + excl;
        s_ends[lane * 8 + 3] = e3 + excl;
        s_ends[lane * 8 + 4] = e4 + excl;
        s_ends[lane * 8 + 5] = e5 + excl;
        s_ends[lane * 8 + 6] = e6 + excl;
        s_ends[lane * 8 + 7] = e7 + excl;
        __syncwarp();

        const int t = frame_base + lane;
        int lo = 0, hi = LR_N;
        #pragma unroll
        for (int it = 0; it < 9; ++it) {
            if (lo < hi) {
                int mid = (lo + hi) >> 1;
                if (s_ends[mid] > t) hi = mid; else lo = mid + 1;
            }
        }
        s_tok[lane] = (lo < LR_N) ? lo : (LR_N - 1);
    }
    __syncthreads();

    const float4* __restrict__ ph_b  = phoneme4 + (size_t)b * LR_N * VPF;
    float4* __restrict__       out_b = out4 + ((size_t)b * LR_T + frame_base) * VPF;

    // ---- path B prep: stage frames 16..31 into smem (LDG -> STS) ----
    #pragma unroll
    for (int i = tid; i < HALF * VPF; i += THREADS) {
        const int f   = i >> 7;
        const int off = i & (VPF - 1);
        s_stage[i] = ph_b[s_tok[HALF + f] * VPF + off];
    }
    __syncthreads();

    // ---- launch path B: one 32KB bulk TMA store for frames 16..31 ----
    if (tid == 0) {
        asm volatile("fence.proxy.async.shared::cta;" ::: "memory");
        char* dst = (char*)(out_b + HALF * VPF);
        asm volatile(
            "cp.async.bulk.global.shared::cta.bulk_group [%0], [%1], %2;"
            :: "l"(dst), "r"(smem_u32(s_stage)), "r"((uint32_t)STAGE_BYTES)
            : "memory");
        asm volatile("cp.async.bulk.commit_group;" ::: "memory");
    }

    // ---- path A: frames 0..15 via LSU while TMA store is in flight ----
    #pragma unroll
    for (int i = tid; i < HALF * VPF; i += THREADS) {
        const int f   = i >> 7;
        const int off = i & (VPF - 1);
        out_b[i] = ph_b[s_tok[f] * VPF + off];
    }

    // ---- drain path B before block exit (smem reuse safety) ----
    if (tid == 0) {
        asm volatile("cp.async.bulk.wait_group 0;" ::: "memory");
    }
    __syncthreads();
}

extern "C" void kernel_launch(void* const* d_in, const int* in_sizes, int n_in,
                              void* d_out, int out_size)
{
    const float4* phoneme4  = (const float4*)d_in[0];   // (B, N, D) f32
    const int*    durations = (const int*)d_in[1];      // (B, N) i32
    float4*       out4      = (float4*)d_out;           // (B, T, D) f32

    dim3 grid(LR_T / FPB, LR_B);    // (64, 16) = 1024 blocks
    length_regulator_dual<<<grid, THREADS>>>(phoneme4, durations, out4);
}

// round 13
// speedup vs baseline: 1.2430x; 1.2430x over previous
#include <cuda_runtime.h>
#include <cuda_bf16.h>
#include <cstdint>

// LengthRegulator: out[b, t, :] = phoneme[b, tok(b,t), :]
// tok(b,t) = searchsorted_right(inclusive_cumsum(durations[b,:]), t), clip N-1.
// Shapes (fixed): B=16, N=256, D=512, T=2048. float32.
//
// Champion geometry (R7/R11: 1024 blocks x 256 threads, 32 frames/block,
// warp-0 shuffle-scan preamble) + 256-bit vector loads/stores (sm_100a+):
// halves L1 wavefronts and store-issue count on the 67MB write stream.

#define LR_B 16
#define LR_N 256
#define LR_D 512
#define LR_T 2048
#define FPB 32
#define THREADS 256
#define VPF 128                       // float4 per 2KB frame
#define V8PF 64                       // 32B-chunks per frame

__global__ __launch_bounds__(THREADS)
void length_regulator_kernel(const float4* __restrict__ phoneme4,
                             const int* __restrict__ durations,
                             float4* __restrict__ out4)
{
    const int b = blockIdx.y;
    const int frame_base = blockIdx.x * FPB;
    const int tid = threadIdx.x;

    __shared__ int s_ends[LR_N];
    __shared__ int s_tok[FPB];

    // Warp 0: shuffle scan (lane owns durations[8L..8L+7]) + binary search.
    if (tid < 32) {
        const int lane = tid;
        const int4* drow = (const int4*)(durations + b * LR_N);
        int4 a = drow[lane * 2 + 0];
        int4 c = drow[lane * 2 + 1];
        int e0 = a.x;
        int e1 = e0 + a.y;
        int e2 = e1 + a.z;
        int e3 = e2 + a.w;
        int e4 = e3 + c.x;
        int e5 = e4 + c.y;
        int e6 = e5 + c.z;
        int e7 = e6 + c.w;
        int x = e7;
        #pragma unroll
        for (int off = 1; off < 32; off <<= 1) {
            int y = __shfl_up_sync(0xffffffffu, x, off);
            if (lane >= off) x += y;
        }
        const int excl = x - e7;
        s_ends[lane * 8 + 0] = e0 + excl;
        s_ends[lane * 8 + 1] = e1 + excl;
        s_ends[lane * 8 + 2] = e2 + excl;
        s_ends[lane * 8 + 3] = e3 + excl;
        s_ends[lane * 8 + 4] = e4 + excl;
        s_ends[lane * 8 + 5] = e5 + excl;
        s_ends[lane * 8 + 6] = e6 + excl;
        s_ends[lane * 8 + 7] = e7 + excl;
        __syncwarp();

        // lower-bound: first n with ends[n] > t (9 steps for N=256)
        const int t = frame_base + lane;
        int lo = 0, hi = LR_N;
        #pragma unroll
        for (int it = 0; it < 9; ++it) {
            if (lo < hi) {
                int mid = (lo + hi) >> 1;
                if (s_ends[mid] > t) hi = mid; else lo = mid + 1;
            }
        }
        s_tok[lane] = (lo < LR_N) ? lo : (LR_N - 1);
    }
    __syncthreads();

    // Copy: 32 frames * 64 x 32B chunks = 2048 chunks per block.
    // Chunk c -> frame (c >> 6), 32B offset (c & 63). Coalesced both sides.
    const float* __restrict__ ph_b =
        (const float*)(phoneme4 + (size_t)b * LR_N * VPF);
    float* __restrict__ out_b =
        (float*)(out4 + ((size_t)b * LR_T + frame_base) * VPF);

    #pragma unroll
    for (int c = tid; c < FPB * V8PF; c += THREADS) {
        const int f   = c >> 6;               // frame within block
        const int off = c & (V8PF - 1);       // 32B chunk within frame
        const float* src = ph_b + ((size_t)s_tok[f] * V8PF + off) * 8;
        float*       dst = out_b + (size_t)c * 8;
        float r0, r1, r2, r3, r4, r5, r6, r7;
        asm volatile(
            "ld.global.nc.v8.f32 {%0,%1,%2,%3,%4,%5,%6,%7}, [%8];"
            : "=f"(r0), "=f"(r1), "=f"(r2), "=f"(r3),
              "=f"(r4), "=f"(r5), "=f"(r6), "=f"(r7)
            : "l"(src));
        asm volatile(
            "st.global.v8.f32 [%0], {%1,%2,%3,%4,%5,%6,%7,%8};"
            :: "l"(dst),
               "f"(r0), "f"(r1), "f"(r2), "f"(r3),
               "f"(r4), "f"(r5), "f"(r6), "f"(r7)
            : "memory");
    }
}

extern "C" void kernel_launch(void* const* d_in, const int* in_sizes, int n_in,
                              void* d_out, int out_size)
{
    const float4* phoneme4  = (const float4*)d_in[0];   // (B, N, D) f32
    const int*    durations = (const int*)d_in[1];      // (B, N) i32
    float4*       out4      = (float4*)d_out;           // (B, T, D) f32

    dim3 grid(LR_T / FPB, LR_B);  // (64, 16) = 1024 blocks
    length_regulator_kernel<<<grid, THREADS>>>(phoneme4, durations, out4);
}

// round 14
// speedup vs baseline: 1.2457x; 1.0022x over previous
#include <cuda_runtime.h>
#include <cuda_bf16.h>

// LengthRegulator: out[b, t, :] = phoneme[b, tok(b,t), :]
// tok(b,t) = searchsorted_right(inclusive_cumsum(durations[b,:]), t), clip N-1.
// Shapes (fixed): B=16, N=256, D=512, T=2048. float32.
//
// FINAL (champion, R7/R11): 1024 blocks x 256 threads, 32 frames/block.
// Warp-0 shuffle-scan preamble (1 barrier), unrolled coalesced float4 copy,
// streaming stores. Empirically on the L2 store-stream roofline (~4.8TB/s
// effective for a 67MB write-only stream): every alternative store path
// (STG.256, TMA bulk, dual LSU+TMA, max-MLP gather) measured >= this.

#define LR_B 16
#define LR_N 256
#define LR_D 512
#define LR_T 2048
#define FRAMES_PER_BLOCK 32
#define THREADS 256
#define VEC_PER_FRAME (LR_D / 4)   // 128 float4 per frame

__global__ __launch_bounds__(THREADS)
void length_regulator_kernel(const float4* __restrict__ phoneme4,
                             const int* __restrict__ durations,
                             float4* __restrict__ out4)
{
    const int b = blockIdx.y;
    const int frame_base = blockIdx.x * FRAMES_PER_BLOCK;
    const int tid = threadIdx.x;

    __shared__ int s_ends[LR_N];
    __shared__ int s_tok[FRAMES_PER_BLOCK];

    // Warp 0: shuffle scan (lane owns durations[8L..8L+7]) + binary search.
    if (tid < 32) {
        const int lane = tid;
        const int4* drow = (const int4*)(durations + b * LR_N);
        int4 a = drow[lane * 2 + 0];
        int4 c = drow[lane * 2 + 1];
        int e0 = a.x;
        int e1 = e0 + a.y;
        int e2 = e1 + a.z;
        int e3 = e2 + a.w;
        int e4 = e3 + c.x;
        int e5 = e4 + c.y;
        int e6 = e5 + c.z;
        int e7 = e6 + c.w;
        int x = e7;
        #pragma unroll
        for (int off = 1; off < 32; off <<= 1) {
            int y = __shfl_up_sync(0xffffffffu, x, off);
            if (lane >= off) x += y;
        }
        const int excl = x - e7;
        s_ends[lane * 8 + 0] = e0 + excl;
        s_ends[lane * 8 + 1] = e1 + excl;
        s_ends[lane * 8 + 2] = e2 + excl;
        s_ends[lane * 8 + 3] = e3 + excl;
        s_ends[lane * 8 + 4] = e4 + excl;
        s_ends[lane * 8 + 5] = e5 + excl;
        s_ends[lane * 8 + 6] = e6 + excl;
        s_ends[lane * 8 + 7] = e7 + excl;
        __syncwarp();

        // lower-bound: first n with ends[n] > t (9 steps for N=256)
        const int t = frame_base + lane;
        int lo = 0, hi = LR_N;
        #pragma unroll
        for (int it = 0; it < 9; ++it) {
            if (lo < hi) {
                int mid = (lo + hi) >> 1;
                if (s_ends[mid] > t) hi = mid; else lo = mid + 1;
            }
        }
        s_tok[lane] = (lo < LR_N) ? lo : (LR_N - 1);
    }
    __syncthreads();

    // Copy: 32 frames * 128 float4, coalesced; streaming stores.
    const float4* __restrict__ ph_b  = phoneme4 + (size_t)b * LR_N * VEC_PER_FRAME;
    float4* __restrict__       out_b = out4 + ((size_t)b * LR_T + frame_base) * VEC_PER_FRAME;

    #pragma unroll
    for (int i = tid; i < FRAMES_PER_BLOCK * VEC_PER_FRAME; i += THREADS) {
        const int f   = i >> 7;              // i / 128
        const int off = i & (VEC_PER_FRAME - 1);
        const float4 v = ph_b[s_tok[f] * VEC_PER_FRAME + off];
        __stcs(&out_b[i], v);                // streaming store (evict-first)
    }
}

extern "C" void kernel_launch(void* const* d_in, const int* in_sizes, int n_in,
                              void* d_out, int out_size)
{
    const float4* phoneme4  = (const float4*)d_in[0];   // (B, N, D) f32
    const int*    durations = (const int*)d_in[1];      // (B, N) i32
    float4*       out4      = (float4*)d_out;           // (B, T, D) f32

    dim3 grid(LR_T / FRAMES_PER_BLOCK, LR_B);  // (64, 16) = 1024 blocks
    length_regulator_kernel<<<grid, THREADS>>>(phoneme4, durations, out4);
}

// round 15
// speedup vs baseline: 1.2484x; 1.0022x over previous
#include <cuda_runtime.h>
#include <cuda_bf16.h>

// LengthRegulator: out[b, t, :] = phoneme[b, tok(b,t), :]
// tok(b,t) = searchsorted_right(inclusive_cumsum(durations[b,:]), t), clip N-1.
// Shapes (fixed): B=16, N=256, D=512, T=2048. float32.
//
// Register-reuse copy: each thread owns ONE column across 16 consecutive
// frames and reloads its float4 only when the frame's token changes
// (warp-uniform branch). Cuts redundant L1TEX read wavefronts ~60-75%.

#define LR_B 16
#define LR_N 256
#define LR_D 512
#define LR_T 2048
#define FPB 32
#define THREADS 256
#define VPF 128                       // float4 per 2KB frame
#define FPT 16                        // frames per thread (FPB/2)

__global__ __launch_bounds__(THREADS)
void length_regulator_kernel(const float4* __restrict__ phoneme4,
                             const int* __restrict__ durations,
                             float4* __restrict__ out4)
{
    const int b = blockIdx.y;
    const int frame_base = blockIdx.x * FPB;
    const int tid = threadIdx.x;

    __shared__ int s_ends[LR_N];
    __shared__ int s_tok[FPB];

    // Warp 0: shuffle scan (lane owns durations[8L..8L+7]) + binary search.
    if (tid < 32) {
        const int lane = tid;
        const int4* drow = (const int4*)(durations + b * LR_N);
        int4 a = drow[lane * 2 + 0];
        int4 c = drow[lane * 2 + 1];
        int e0 = a.x;
        int e1 = e0 + a.y;
        int e2 = e1 + a.z;
        int e3 = e2 + a.w;
        int e4 = e3 + c.x;
        int e5 = e4 + c.y;
        int e6 = e5 + c.z;
        int e7 = e6 + c.w;
        int x = e7;
        #pragma unroll
        for (int off = 1; off < 32; off <<= 1) {
            int y = __shfl_up_sync(0xffffffffu, x, off);
            if (lane >= off) x += y;
        }
        const int excl = x - e7;
        s_ends[lane * 8 + 0] = e0 + excl;
        s_ends[lane * 8 + 1] = e1 + excl;
        s_ends[lane * 8 + 2] = e2 + excl;
        s_ends[lane * 8 + 3] = e3 + excl;
        s_ends[lane * 8 + 4] = e4 + excl;
        s_ends[lane * 8 + 5] = e5 + excl;
        s_ends[lane * 8 + 6] = e6 + excl;
        s_ends[lane * 8 + 7] = e7 + excl;
        __syncwarp();

        // lower-bound: first n with ends[n] > t (9 steps for N=256)
        const int t = frame_base + lane;
        int lo = 0, hi = LR_N;
        #pragma unroll
        for (int it = 0; it < 9; ++it) {
            if (lo < hi) {
                int mid = (lo + hi) >> 1;
                if (s_ends[mid] > t) hi = mid; else lo = mid + 1;
            }
        }
        s_tok[lane] = (lo < LR_N) ? lo : (LR_N - 1);
    }
    __syncthreads();

    // Thread owns column (tid & 127) for frames [half*16, half*16+16).
    // All 32 lanes of a warp share the same frame set -> the token-change
    // branch is warp-uniform (no divergence); stores stay 512B-coalesced.
    const int col  = tid & (VPF - 1);
    const int half = tid >> 7;            // 0 or 1
    const int f0   = half * FPT;

    // preload this thread's 16 token indices (4 x LDS.128)
    int tk[FPT];
    #pragma unroll
    for (int q = 0; q < FPT / 4; ++q) {
        int4 v = ((const int4*)s_tok)[half * (FPT / 4) + q];
        tk[q * 4 + 0] = v.x;
        tk[q * 4 + 1] = v.y;
        tk[q * 4 + 2] = v.z;
        tk[q * 4 + 3] = v.w;
    }

    const float4* __restrict__ ph_col =
        phoneme4 + (size_t)b * LR_N * VPF + col;
    float4* __restrict__ out_col =
        out4 + ((size_t)b * LR_T + frame_base + f0) * VPF + col;

    float4 v = ph_col[(size_t)tk[0] * VPF];
    __stcs(&out_col[0], v);
    #pragma unroll
    for (int j = 1; j < FPT; ++j) {
        if (tk[j] != tk[j - 1])               // warp-uniform
            v = ph_col[(size_t)tk[j] * VPF];
        __stcs(&out_col[(size_t)j * VPF], v);
    }
}

extern "C" void kernel_launch(void* const* d_in, const int* in_sizes, int n_in,
                              void* d_out, int out_size)
{
    const float4* phoneme4  = (const float4*)d_in[0];   // (B, N, D) f32
    const int*    durations = (const int*)d_in[1];      // (B, N) i32
    float4*       out4      = (float4*)d_out;           // (B, T, D) f32

    dim3 grid(LR_T / FPB, LR_B);  // (64, 16) = 1024 blocks
    length_regulator_kernel<<<grid, THREADS>>>(phoneme4, durations, out4);
}